// round 14
// baseline (speedup 1.0000x reference)
#include <cuda_runtime.h>
#include <cuda_fp16.h>

// RoiAlign: feature_map (4, 256, 50, 50) f32, boxes (512,4) f32, box_idx (512) i32
// Output: (512, 256, 14, 14) f32
//
// R14 restructure: (1) transpose fm to NHWC fp16 in a static scratch buffer,
// (2) direct bilinear gather where each cell read is 16 B of 8 contiguous
// channels (LDG.128). No smem staging, no barriers in the hot kernel; MLP
// (32 loads in flight/thread) hides L2 latency.

#define CROP    14
#define NPIX    (CROP * CROP)      // 196
#define FM_H    50
#define FM_W    50
#define FM_HW   (FM_H * FM_W)      // 2500
#define NCHAN   256
#define NC2     (NCHAN / 2)        // 128 half2 per pixel
#define NBOX    512
#define CSPLIT  2
#define CPB     (NCHAN / CSPLIT)   // 128 channels per gather block
#define NCG     (CPB / 8)          // 16 groups of 8 channels

// Static scratch: 4 * 2500 * 128 half2 = 5.12 MB
__device__ __half2 g_nhwc[4 * FM_HW * NC2];

// ---------------- Kernel 1: NCHW f32 -> NHWC fp16 transpose ----------------
__global__ __launch_bounds__(256) void transpose_kernel(const float* __restrict__ fm)
{
    __shared__ float tile[32][33];
    const int n  = blockIdx.z;
    const int s0 = blockIdx.x * 32;      // spatial (h*50+w) base
    const int c0 = blockIdx.y * 32;      // channel base
    const int tx = threadIdx.x;          // 32
    const int ty = threadIdx.y;          // 8

    #pragma unroll
    for (int i = ty; i < 32; i += 8) {
        const int s = s0 + tx;
        tile[i][tx] = (s < FM_HW)
            ? __ldg(fm + ((size_t)n * NCHAN + c0 + i) * FM_HW + s) : 0.0f;
    }
    __syncthreads();

    if (tx < 16) {
        #pragma unroll
        for (int j = ty; j < 32; j += 8) {
            const int s = s0 + j;
            if (s < FM_HW) {
                __half2 h = __floats2half2_rn(tile[2 * tx][j], tile[2 * tx + 1][j]);
                g_nhwc[((size_t)n * FM_HW + s) * NC2 + (c0 >> 1) + tx] = h;
            }
        }
    }
}

// ---------------- Kernel 2: direct channel-vectorized gather ----------------
__global__ __launch_bounds__(NPIX, 6) void roi_gather_kernel(
    const float* __restrict__ boxes,
    const int*   __restrict__ box_idx,
    float*       __restrict__ out)
{
    const int m   = blockIdx.x;              // box
    const int cb  = blockIdx.y * CPB;        // channel base (0 or 128)
    const int tid = threadIdx.x;             // pixel 0..195

    const int iy = tid / CROP;
    const int ix = tid - iy * CROP;

    const float inv_stride = 1.0f / 16.0f;
    const float inv_span   = 1.0f / (float)(CROP - 1);
    const float bx1 = boxes[m * 4 + 0] * inv_stride;
    const float by1 = boxes[m * 4 + 1] * inv_stride;
    const float bx2 = boxes[m * 4 + 2] * inv_stride;
    const float by2 = boxes[m * 4 + 3] * inv_stride;

    const float ys = by1 + (float)iy * (by2 - by1) * inv_span;
    const float xs = bx1 + (float)ix * (bx2 - bx1) * inv_span;

    const float y0f = floorf(ys);
    const float x0f = floorf(xs);
    const int y0 = min(max((int)y0f, 0), FM_H - 1);
    const int x0 = min(max((int)x0f, 0), FM_W - 1);
    const int y1 = min(y0 + 1, FM_H - 1);
    const int x1 = min(x0 + 1, FM_W - 1);
    const float wy = ys - y0f;
    const float wx = xs - x0f;
    const float v  = (ys >= 0.0f && ys <= (float)(FM_H - 1) &&
                      xs >= 0.0f && xs <= (float)(FM_W - 1)) ? 1.0f : 0.0f;

    const __half2 hw00 = __float2half2_rn((1.0f - wx) * (1.0f - wy) * v);
    const __half2 hw01 = __float2half2_rn(wx * (1.0f - wy) * v);
    const __half2 hw10 = __float2half2_rn((1.0f - wx) * wy * v);
    const __half2 hw11 = __float2half2_rn(wx * wy * v);

    const int bi = box_idx[m];
    const size_t pix_base = (size_t)bi * FM_HW;
    const size_t ch_off   = (size_t)(cb >> 1);     // half2 offset

    // 16-byte cell pointers (8 channels per uint4), cg-indexable.
    const uint4* p00 = (const uint4*)(g_nhwc + (pix_base + y0 * FM_W + x0) * NC2 + ch_off);
    const uint4* p01 = (const uint4*)(g_nhwc + (pix_base + y0 * FM_W + x1) * NC2 + ch_off);
    const uint4* p10 = (const uint4*)(g_nhwc + (pix_base + y1 * FM_W + x0) * NC2 + ch_off);
    const uint4* p11 = (const uint4*)(g_nhwc + (pix_base + y1 * FM_W + x1) * NC2 + ch_off);

    float* __restrict__ o =
        out + (size_t)m * NCHAN * NPIX + (size_t)cb * NPIX + tid;

    #pragma unroll 4
    for (int cg = 0; cg < NCG; ++cg) {
        const uint4 A = __ldg(p00 + cg);
        const uint4 B = __ldg(p01 + cg);
        const uint4 C = __ldg(p10 + cg);
        const uint4 D = __ldg(p11 + cg);

        float* oc = o + cg * 8 * NPIX;

        #pragma unroll
        for (int j = 0; j < 4; ++j) {
            const __half2 a = ((const __half2*)&A)[j];
            const __half2 b = ((const __half2*)&B)[j];
            const __half2 c = ((const __half2*)&C)[j];
            const __half2 d = ((const __half2*)&D)[j];

            __half2 u = __hfma2(b, hw01, __hmul2(a, hw00));
            __half2 w = __hfma2(d, hw11, __hmul2(c, hw10));
            __half2 r = __hadd2(u, w);
            const float2 rf = __half22float2(r);
            oc[(2 * j)     * NPIX] = rf.x;
            oc[(2 * j + 1) * NPIX] = rf.y;
        }
    }
}

extern "C" void kernel_launch(void* const* d_in, const int* in_sizes, int n_in,
                              void* d_out, int out_size)
{
    const float* fm     = (const float*)d_in[0];
    const float* boxes  = (const float*)d_in[1];
    const int*   boxidx = (const int*)d_in[2];
    float*       out    = (float*)d_out;

    dim3 tgrid((FM_HW + 31) / 32, NCHAN / 32, 4);   // (79, 8, 4)
    transpose_kernel<<<tgrid, dim3(32, 8)>>>(fm);

    dim3 ggrid(NBOX, CSPLIT);                        // (512, 2)
    roi_gather_kernel<<<ggrid, NPIX>>>(boxes, boxidx, out);
}

// round 16
// speedup vs baseline: 2.0541x; 2.0541x over previous
#include <cuda_runtime.h>
#include <cuda_fp16.h>

// RoiAlign: feature_map (4, 256, 50, 50) f32, boxes (512,4) f32, box_idx (512) i32
// Output: (512, 256, 14, 14) f32
//
// R16 = R15 resubmitted (prior round was an infra failure, kernel untested).
// R12 base (fp16 smem staging + half2 tree compute + depth-1 pipeline, 32 regs,
// occ ~87%) + row stride padded 16 -> 17 cells so window rows no longer alias
// to the same banks (256B row stride -> bank shift 0; 272B -> shift 4).

#define CROP    14
#define NPIX    (CROP * CROP)      // 196
#define FM_H    50
#define FM_W    50
#define FM_HW   (FM_H * FM_W)      // 2500
#define NCHAN   256
#define NBOX    512
#define CPB     32                 // channels per block
#define NCG8    (CPB / 8)          // 4 groups of 8 channels
#define WIN     16
#define WSTR    17                 // padded row stride in cells (bank shift 4)
#define NCELLP  (WIN * WSTR)       // 272 cells per cg region
#define THREADS 224                // 7 full warps

struct alignas(16) h2x4 {          // 8 fp16 values = one 16-byte smem cell
    __half2 a, b, c, d;
};

__global__ __launch_bounds__(THREADS, 9) void roi_align_kernel(
    const float* __restrict__ fm,
    const float* __restrict__ boxes,
    const int*   __restrict__ box_idx,
    float*       __restrict__ out)
{
    __shared__ h2x4 s4[NCG8 * NCELLP];   // 4 * 272 * 16 B = 17,408 B

    const int m   = blockIdx.x;               // box
    const int cb  = blockIdx.y * CPB;         // channel base
    const int tid = threadIdx.x;

    // ---- Per-box geometry ----
    const float inv_stride = 1.0f / 16.0f;
    const float inv_span   = 1.0f / (float)(CROP - 1);
    const float bx1 = boxes[m * 4 + 0] * inv_stride;
    const float by1 = boxes[m * 4 + 1] * inv_stride;
    const float bx2 = boxes[m * 4 + 2] * inv_stride;
    const float by2 = boxes[m * 4 + 3] * inv_stride;

    const int ystart = min(max((int)floorf(by1), 0), FM_H - 1);
    const int xstart = min(max((int)floorf(bx1), 0), FM_W - 1);

    // Trimmed staging extents (+margin for fp rounding at far edge).
    const int yendc = min(max((int)floorf(by2), 0), FM_H - 1);
    const int xendc = min(max((int)floorf(bx2), 0), FM_W - 1);
    const int wyn = min(yendc - ystart + 3, WIN);
    const int wxn = min(xendc - xstart + 3, WIN);
    const int cells = wyn << 4;               // task space: wyn rows x 16 slots

    const int bi = box_idx[m];
    const float* __restrict__ fbase =
        fm + (size_t)bi * NCHAN * FM_HW + (size_t)cb * FM_HW;

    // ---- Per-pixel sampling state (valid for tid < 196) ----
    const int iy = tid / CROP;
    const int ix = tid - iy * CROP;

    const float ys = by1 + (float)iy * (by2 - by1) * inv_span;
    const float xs = bx1 + (float)ix * (bx2 - bx1) * inv_span;

    const float y0f = floorf(ys);
    const float x0f = floorf(xs);
    const int y0 = min(max((int)y0f, 0), FM_H - 1);
    const int x0 = min(max((int)x0f, 0), FM_W - 1);
    const int y1 = min(y0 + 1, FM_H - 1);
    const int x1 = min(x0 + 1, FM_W - 1);
    const float wy = ys - y0f;
    const float wx = xs - x0f;
    const float v  = (ys >= 0.0f && ys <= (float)(FM_H - 1) &&
                      xs >= 0.0f && xs <= (float)(FM_W - 1)) ? 1.0f : 0.0f;

    const int l00 = (y0 - ystart) * WSTR + (x0 - xstart);
    const int dx  = x1 - x0;               // 0 or 1
    const int dyc = (y1 - y0) * WSTR;      // 0 or 17

    const __half2 hw00 = __float2half2_rn((1.0f - wx) * (1.0f - wy) * v);
    const __half2 hw01 = __float2half2_rn(wx * (1.0f - wy) * v);
    const __half2 hw10 = __float2half2_rn((1.0f - wx) * wy * v);
    const __half2 hw11 = __float2half2_rn(wx * wy * v);

    float* __restrict__ o =
        out + (size_t)m * NCHAN * NPIX + (size_t)cb * NPIX + tid;

    // ---- Staging helper (16 tasks/row; 8x LDG.32 per task; padded store) ----
    auto stage_cg = [&](int cg) {
        const float* __restrict__ fc = fbase + cg * 8 * FM_HW;
        for (int r = tid; r < cells; r += THREADS) {
            const int ry = r >> 4;
            const int rx = r & 15;
            if (rx < wxn) {
                const int gy = min(ystart + ry, FM_H - 1);
                const int gx = min(xstart + rx, FM_W - 1);
                const float* p = fc + gy * FM_W + gx;
                h2x4 packed;
                packed.a = __float22half2_rn(make_float2(__ldg(p),             __ldg(p + FM_HW)));
                packed.b = __float22half2_rn(make_float2(__ldg(p + 2 * FM_HW), __ldg(p + 3 * FM_HW)));
                packed.c = __float22half2_rn(make_float2(__ldg(p + 4 * FM_HW), __ldg(p + 5 * FM_HW)));
                packed.d = __float22half2_rn(make_float2(__ldg(p + 6 * FM_HW), __ldg(p + 7 * FM_HW)));
                s4[cg * NCELLP + ry * WSTR + rx] = packed;
            }
        }
    };

    // ---- Depth-1 pipeline: stage(cg+1) issued before compute(cg) ----
    stage_cg(0);
    __syncthreads();

    #pragma unroll
    for (int cg = 0; cg < NCG8; ++cg) {
        if (cg + 1 < NCG8) stage_cg(cg + 1);

        if (tid < NPIX) {
            const h2x4* sc = s4 + cg * NCELLP;
            const h2x4 pa = sc[l00];
            const h2x4 pb = sc[l00 + dx];
            const h2x4 pc = sc[l00 + dyc];
            const h2x4 pd = sc[l00 + dyc + dx];

            float* oc = o + cg * 8 * NPIX;

            #pragma unroll
            for (int j = 0; j < 4; ++j) {
                __half2 u = __hfma2((&pb.a)[j], hw01, __hmul2((&pa.a)[j], hw00));
                __half2 w = __hfma2((&pd.a)[j], hw11, __hmul2((&pc.a)[j], hw10));
                __half2 r = __hadd2(u, w);
                const float2 rf = __half22float2(r);
                oc[(2 * j)     * NPIX] = rf.x;
                oc[(2 * j + 1) * NPIX] = rf.y;
            }
        }
        if (cg + 1 < NCG8) __syncthreads();
    }
}

extern "C" void kernel_launch(void* const* d_in, const int* in_sizes, int n_in,
                              void* d_out, int out_size)
{
    const float* fm     = (const float*)d_in[0];
    const float* boxes  = (const float*)d_in[1];
    const int*   boxidx = (const int*)d_in[2];
    float*       out    = (float*)d_out;

    dim3 grid(NBOX, NCHAN / CPB);   // (512, 8) = 4096 blocks
    roi_align_kernel<<<grid, THREADS>>>(fm, boxes, boxidx, out);
}